// round 14
// baseline (speedup 1.0000x reference)
#include <cuda_runtime.h>

#define NB    8
#define HW    56
#define CDIM  128
#define P2    49
#define PIX   64
#define QKC   128
#define KVC   256
#define OUTC  384
#define TOK   (NB*HW*HW)   /* 25088 */
#define NTOPK 4
#define HEADS 8
#define HD    16

typedef unsigned long long u64t;

// ---- packed f32x2 helpers (Blackwell sm_103a) ------------------------------
__device__ __forceinline__ u64t pack2(float lo, float hi) {
    u64t r; asm("mov.b64 %0, {%1, %2};" : "=l"(r) : "f"(lo), "f"(hi)); return r;
}
__device__ __forceinline__ void unpack2(u64t v, float& lo, float& hi) {
    asm("mov.b64 {%0, %1}, %2;" : "=f"(lo), "=f"(hi) : "l"(v));
}
__device__ __forceinline__ void fma2(u64t& d, u64t a, u64t b) {
    asm("fma.rn.f32x2 %0, %1, %2, %0;" : "+l"(d) : "l"(a), "l"(b));
}
__device__ __forceinline__ void mul2(u64t& d, u64t a) {
    asm("mul.rn.f32x2 %0, %0, %1;" : "+l"(d) : "l"(a));
}
__device__ __forceinline__ float ex2a(float x) {
    float r; asm("ex2.approx.f32 %0, %1;" : "=f"(r) : "f"(x)); return r;
}
__device__ __forceinline__ void cp16(void* smem, const void* gmem) {
    unsigned s = (unsigned)__cvta_generic_to_shared(smem);
    asm volatile("cp.async.cg.shared.global [%0], [%1], 16;" :: "r"(s), "l"(gmem));
}
__device__ __forceinline__ void cp_commit() {
    asm volatile("cp.async.commit_group;");
}
__device__ __forceinline__ void cp_wait1() {
    asm volatile("cp.async.wait_group 1;");
}

// ---------------- scratch (device globals; no runtime allocation) ----------
__device__ float g_q   [2][NB][P2][PIX][QKC];   // per-branch q, windowed
__device__ float g_kv  [2][NB][P2][PIX][KVC];   // per-branch kv, windowed
__device__ float g_vimg[2][NB][HW][HW][CDIM];   // v in image layout (for LePE)
__device__ float g_qwin[2][NB][P2][QKC];
__device__ float g_kwin[2][NB][P2][QKC];
__device__ int   g_top [2][NB][P2][NTOPK];

// ---------------- 1. QKV projection GEMM (both branches, f32x2) ------------
// 128x128 tile, 16-wide k-tiles (2-barrier phases), A staged pre-duplicated
// as u64 pairs so the inner loop has zero pack movs.
__global__ void __launch_bounds__(256) qkv_kernel(
        const float* __restrict__ x, const float* __restrict__ y,
        const float* __restrict__ wx, const float* __restrict__ bx,
        const float* __restrict__ wy, const float* __restrict__ by)
{
    const int br = blockIdx.z;
    const float* __restrict__ A  = br ? y  : x;
    const float* __restrict__ W  = br ? wy : wx;
    const float* __restrict__ Bv = br ? by : bx;

    const int t0 = blockIdx.y * 128;   // token tile
    const int c0 = blockIdx.x * 128;   // output-channel tile

    __shared__ u64t  As2[16][132];     // duplicated A: As2[k][row] = (a,a)
    __shared__ float Bs [16][136];     // Bs[k][col]

    const int tx = threadIdx.x, ty = threadIdx.y;   // 16 x 16
    const int tid = ty * 16 + tx;

    // load indices: A 128 rows x 16 k (2 thr/row, 8 k each);
    //               W 16 rows x 128 cols (16 thr/row, 8 cols each)
    const int arow = tid >> 1,  ak0 = (tid & 1)  * 8;
    const int brow = tid >> 4,  bc0 = (tid & 15) * 8;

    u64t acc[8][4];
    #pragma unroll
    for (int i = 0; i < 8; i++)
        #pragma unroll
        for (int j = 0; j < 4; j++) acc[i][j] = 0ull;

    for (int k0 = 0; k0 < 128; k0 += 16) {
        {
            float4 a0 = *reinterpret_cast<const float4*>(&A[(long)(t0 + arow) * CDIM + k0 + ak0]);
            float4 a1 = *reinterpret_cast<const float4*>(&A[(long)(t0 + arow) * CDIM + k0 + ak0 + 4]);
            As2[ak0 + 0][arow] = pack2(a0.x, a0.x);
            As2[ak0 + 1][arow] = pack2(a0.y, a0.y);
            As2[ak0 + 2][arow] = pack2(a0.z, a0.z);
            As2[ak0 + 3][arow] = pack2(a0.w, a0.w);
            As2[ak0 + 4][arow] = pack2(a1.x, a1.x);
            As2[ak0 + 5][arow] = pack2(a1.y, a1.y);
            As2[ak0 + 6][arow] = pack2(a1.z, a1.z);
            As2[ak0 + 7][arow] = pack2(a1.w, a1.w);
            float4 w0 = *reinterpret_cast<const float4*>(&W[(long)(k0 + brow) * OUTC + c0 + bc0]);
            float4 w1 = *reinterpret_cast<const float4*>(&W[(long)(k0 + brow) * OUTC + c0 + bc0 + 4]);
            *reinterpret_cast<float4*>(&Bs[brow][bc0])     = w0;
            *reinterpret_cast<float4*>(&Bs[brow][bc0 + 4]) = w1;
        }
        __syncthreads();

        #pragma unroll
        for (int kk = 0; kk < 16; kk++) {
            ulonglong2 A0 = *reinterpret_cast<const ulonglong2*>(&As2[kk][ty*4]);
            ulonglong2 A1 = *reinterpret_cast<const ulonglong2*>(&As2[kk][ty*4 + 2]);
            ulonglong2 A2 = *reinterpret_cast<const ulonglong2*>(&As2[kk][64 + ty*4]);
            ulonglong2 A3 = *reinterpret_cast<const ulonglong2*>(&As2[kk][64 + ty*4 + 2]);
            ulonglong2 b0 = *reinterpret_cast<const ulonglong2*>(&Bs[kk][tx*4]);
            ulonglong2 b1 = *reinterpret_cast<const ulonglong2*>(&Bs[kk][64 + tx*4]);
            u64t ap[8] = { A0.x, A0.y, A1.x, A1.y, A2.x, A2.y, A3.x, A3.y };
            u64t bp[4] = { b0.x, b0.y, b1.x, b1.y };
            #pragma unroll
            for (int i = 0; i < 8; i++)
                #pragma unroll
                for (int j = 0; j < 4; j++)
                    fma2(acc[i][j], ap[i], bp[j]);
        }
        __syncthreads();
    }

    // epilogue: scatter into windowed layouts
    #pragma unroll
    for (int i = 0; i < 8; i++) {
        int t   = t0 + (i < 4 ? ty*4 + i : 64 + ty*4 + i - 4);
        int n   = t / (HW*HW);
        int rem = t % (HW*HW);
        int Y = rem / HW, X = rem % HW;
        int p   = (Y >> 3) * 7 + (X >> 3);
        int pix = (Y & 7) * 8 + (X & 7);
        #pragma unroll
        for (int jb = 0; jb < 4; jb++) {
            float v0, v1;
            unpack2(acc[i][jb], v0, v1);
            int cbase = c0 + (jb < 2 ? tx*4 + jb*2 : 64 + tx*4 + (jb-2)*2);
            #pragma unroll
            for (int h = 0; h < 2; h++) {
                int cc = cbase + h;
                float v = (h ? v1 : v0) + Bv[cc];
                if (cc < QKC) {
                    g_q[br][n][p][pix][cc] = v;
                } else {
                    g_kv[br][n][p][pix][cc - QKC] = v;
                    if (cc >= 256) g_vimg[br][n][Y][X][cc - 256] = v;
                }
            }
        }
    }
}

// ---------------- 2. window means ------------------------------------------
__global__ void mean_kernel()
{
    int b   = blockIdx.x;               // 2*NB*P2
    int br  = b / (NB*P2);
    int rem = b % (NB*P2);
    int n = rem / P2, p = rem % P2;
    int c = threadIdx.x;                // 128
    float sq = 0.f, sk = 0.f;
    #pragma unroll 8
    for (int pix = 0; pix < PIX; pix++) {
        sq += g_q [br][n][p][pix][c];
        sk += g_kv[br][n][p][pix][c];
    }
    g_qwin[br][n][p][c] = sq * (1.f/64.f);
    g_kwin[br][n][p][c] = sk * (1.f/64.f);
}

// ---------------- 3. routing: exact top-4 (jax top_k ordering) -------------
__global__ void route_kernel()
{
    int b   = blockIdx.x;               // 2*NB*P2
    int br  = b / (NB*P2);
    int rem = b % (NB*P2);
    int n = rem / P2, p = rem % P2;

    __shared__ float lg[P2];
    int j = threadIdx.x;                // 64 threads
    if (j < P2) {
        float d = 0.f;
        #pragma unroll 8
        for (int c = 0; c < QKC; c++)
            d += g_qwin[br][n][p][c] * g_kwin[br][n][j][c];
        lg[j] = d;   // positive scale doesn't change ordering
    }
    __syncthreads();
    if (threadIdx.x == 0) {
        bool used[P2];
        #pragma unroll
        for (int q = 0; q < P2; q++) used[q] = false;
        for (int k = 0; k < NTOPK; k++) {
            float best = -3.4e38f; int bi = 0;
            for (int q = 0; q < P2; q++)
                if (!used[q] && lg[q] > best) { best = lg[q]; bi = q; }
            used[bi] = true;
            g_top[br][n][p][k] = bi;
        }
    }
}

// ---------------- 4. fused gather + cross attention ------------------------
// Block = (n,p,dir) x head-pair; warp = one head, fully independent:
// per-warp double-buffered cp.async staging (32-key stages), no block barriers.
// Thread = 2 queries (lane, lane+32), all math packed f32x2.
// Softmax without max-shift; scale*log2e folded into q (single EX2 per key).
__global__ void __launch_bounds__(64, 8) attn_kernel(float* __restrict__ out)
{
    const int np = blockIdx.x;          // 392
    const int n = np / P2, p = np % P2;
    const int hp  = blockIdx.y;         // head pair 0..3
    const int dir = blockIdx.z;
    const int Abr = dir ^ 1;            // dir0: A=1, dir1: A=0
    const int Bbr = dir;                // dir0: B=0, dir1: B=1

    // per-warp staging: [warp][buf][32 rows x 4 x 16B]
    __shared__ ulonglong2 kbuf[2][2][128];
    __shared__ ulonglong2 vbuf[2][2][128];
    __shared__ int swA[4], swB[4];

    const int tid  = threadIdx.x;       // 64
    const int warp = tid >> 5;
    const int lane = tid & 31;
    const int head = hp * 2 + warp;
    const int hc   = head * HD;

    if (tid < 4)      swA[tid]   = g_top[Abr][n][p][tid];
    else if (tid < 8) swB[tid-4] = g_top[Bbr][n][p][tid-4];

    const float* __restrict__ kvA = &g_kv[Abr][n][0][0][0];
    const float* __restrict__ kvB = &g_kv[Bbr][n][0][0][0];

    // load the two queries (pixels lane, lane+32), pre-scaled by scale*log2e
    const float qsc = 0.0883883476483184405f * 1.44269504088896340736f;
    const u64t qsc2 = pack2(qsc, qsc);
    u64t qA[8], qB[8];
    {
        const ulonglong2* qp = (const ulonglong2*)&g_q[Abr][n][p][lane][hc];
        #pragma unroll
        for (int i = 0; i < 4; i++) { ulonglong2 t = qp[i]; qA[2*i] = t.x; qA[2*i+1] = t.y; }
        qp = (const ulonglong2*)&g_q[Abr][n][p][lane + 32][hc];
        #pragma unroll
        for (int i = 0; i < 4; i++) { ulonglong2 t = qp[i]; qB[2*i] = t.x; qB[2*i+1] = t.y; }
        #pragma unroll
        for (int i = 0; i < 8; i++) { mul2(qA[i], qsc2); mul2(qB[i], qsc2); }
    }
    __syncthreads();                    // widx visible to all warps (only block barrier)

    // hoist gathered-window base pointers into registers (per-thread)
    const float* baseA[4];
    const float* baseB[4];
    #pragma unroll
    for (int kk = 0; kk < 4; kk++) {
        baseA[kk] = kvA + (long)swA[kk] * PIX * KVC + hc;
        baseB[kk] = kvB + (long)swB[kk] * PIX * KVC + QKC + hc;
    }

    // prefetch helper: stage st (32 keys) into buffer b
    auto prefetch = [&](int st, int b) {
        #pragma unroll
        for (int l = 0; l < 4; l++) {
            int e   = lane + l * 32;    // 0..127 float4 slots
            int row = e >> 2, c4 = e & 3;
            int grow = st * 32 + row;
            int kk = grow >> 6, pix = grow & 63;
            long off = (long)pix * KVC + c4 * 4;
            cp16(&kbuf[warp][b][e], baseA[kk] + off);
            cp16(&vbuf[warp][b][e], baseB[kk] + off);
        }
    };

    float sA = 0.f, sB = 0.f;
    u64t oA[8], oB[8];
    #pragma unroll
    for (int i = 0; i < 8; i++) { oA[i] = 0ull; oB[i] = 0ull; }

    prefetch(0, 0);
    cp_commit();

    for (int st = 0; st < 8; st++) {
        if (st < 7) prefetch(st + 1, (st + 1) & 1);
        cp_commit();                    // may be an empty group on st==7
        cp_wait1();                     // stage st complete (<=1 group pending)
        __syncwarp();

        const ulonglong2* kb = &kbuf[warp][st & 1][0];
        const ulonglong2* vb = &vbuf[warp][st & 1][0];

        #pragma unroll 8
        for (int j = 0; j < 32; j++) {
            const ulonglong2* kr = kb + j * 4;
            ulonglong2 r0 = kr[0], r1 = kr[1], r2 = kr[2], r3 = kr[3];
            u64t dA = 0ull, dB = 0ull;
            fma2(dA, qA[0], r0.x); fma2(dB, qB[0], r0.x);
            fma2(dA, qA[1], r0.y); fma2(dB, qB[1], r0.y);
            fma2(dA, qA[2], r1.x); fma2(dB, qB[2], r1.x);
            fma2(dA, qA[3], r1.y); fma2(dB, qB[3], r1.y);
            fma2(dA, qA[4], r2.x); fma2(dB, qB[4], r2.x);
            fma2(dA, qA[5], r2.y); fma2(dB, qB[5], r2.y);
            fma2(dA, qA[6], r3.x); fma2(dB, qB[6], r3.x);
            fma2(dA, qA[7], r3.y); fma2(dB, qB[7], r3.y);
            float l0, l1, lgA, lgB;
            unpack2(dA, l0, l1); lgA = l0 + l1;
            unpack2(dB, l0, l1); lgB = l0 + l1;
            float pA = ex2a(lgA);       // exp(logit), base-2 folded into q
            float pB = ex2a(lgB);
            sA += pA; sB += pB;
            u64t pA2 = pack2(pA, pA), pB2 = pack2(pB, pB);
            const ulonglong2* vr = vb + j * 4;
            ulonglong2 v0 = vr[0], v1 = vr[1], v2 = vr[2], v3 = vr[3];
            fma2(oA[0], pA2, v0.x); fma2(oB[0], pB2, v0.x);
            fma2(oA[1], pA2, v0.y); fma2(oB[1], pB2, v0.y);
            fma2(oA[2], pA2, v1.x); fma2(oB[2], pB2, v1.x);
            fma2(oA[3], pA2, v1.y); fma2(oB[3], pB2, v1.y);
            fma2(oA[4], pA2, v2.x); fma2(oB[4], pB2, v2.x);
            fma2(oA[5], pA2, v2.y); fma2(oB[5], pB2, v2.y);
            fma2(oA[6], pA2, v3.x); fma2(oB[6], pB2, v3.x);
            fma2(oA[7], pA2, v3.y); fma2(oB[7], pB2, v3.y);
        }
        __syncwarp();                   // all lanes done reading before next overwrite
    }

    const float invA = 1.f / sA, invB = 1.f / sB;
    u64t iA2 = pack2(invA, invA), iB2 = pack2(invB, invB);
    #pragma unroll
    for (int i = 0; i < 8; i++) { mul2(oA[i], iA2); mul2(oB[i], iB2); }

    const int Yb = (p / 7) * 8, Xb = (p % 7) * 8;
    {
        int Y = Yb + (lane >> 3), X = Xb + (lane & 7);
        float* op = out + (long)dir * TOK * CDIM
                  + ((long)(n * HW + Y) * HW + X) * CDIM + hc;
        ulonglong2* o2 = (ulonglong2*)op;
        o2[0] = make_ulonglong2(oA[0], oA[1]);
        o2[1] = make_ulonglong2(oA[2], oA[3]);
        o2[2] = make_ulonglong2(oA[4], oA[5]);
        o2[3] = make_ulonglong2(oA[6], oA[7]);
    }
    {
        int qpix = lane + 32;
        int Y = Yb + (qpix >> 3), X = Xb + (qpix & 7);
        float* op = out + (long)dir * TOK * CDIM
                  + ((long)(n * HW + Y) * HW + X) * CDIM + hc;
        ulonglong2* o2 = (ulonglong2*)op;
        o2[0] = make_ulonglong2(oB[0], oB[1]);
        o2[1] = make_ulonglong2(oB[2], oB[3]);
        o2[2] = make_ulonglong2(oB[4], oB[5]);
        o2[3] = make_ulonglong2(oB[6], oB[7]);
    }
}

// ---------------- 5. LePE depthwise 3x3 conv (accumulate into out) ---------
__global__ void lepe_kernel(const float* __restrict__ wlx, const float* __restrict__ blx,
                            const float* __restrict__ wly, const float* __restrict__ bly,
                            float* __restrict__ out)
{
    int b   = blockIdx.x;               // 2*NB*HW*HW
    int br  = b / (NB*HW*HW);
    int rem = b % (NB*HW*HW);
    int n  = rem / (HW*HW);
    int r2 = rem % (HW*HW);
    int Y = r2 / HW, X = r2 % HW;
    int c = threadIdx.x;                // 128
    const float* __restrict__ wl = br ? wly : wlx;
    const float* __restrict__ bl = br ? bly : blx;

    float acc = bl[c];
    #pragma unroll
    for (int dy = 0; dy < 3; dy++) {
        int Yn = Y + dy - 1;
        if (Yn < 0 || Yn >= HW) continue;
        #pragma unroll
        for (int dx = 0; dx < 3; dx++) {
            int Xn = X + dx - 1;
            if (Xn < 0 || Xn >= HW) continue;
            acc += g_vimg[br][n][Yn][Xn][c] * wl[c*9 + dy*3 + dx];
        }
    }
    long off = (long)br * TOK * CDIM + (long)rem * CDIM + c;
    out[off] += acc;
}

// ---------------- launch ----------------------------------------------------
extern "C" void kernel_launch(void* const* d_in, const int* in_sizes, int n_in,
                              void* d_out, int out_size)
{
    const float* x   = (const float*)d_in[0];
    const float* y   = (const float*)d_in[1];
    const float* wqx = (const float*)d_in[2];
    const float* bqx = (const float*)d_in[3];
    const float* wqy = (const float*)d_in[4];
    const float* bqy = (const float*)d_in[5];
    const float* wlx = (const float*)d_in[6];
    const float* blx = (const float*)d_in[7];
    const float* wly = (const float*)d_in[8];
    const float* bly = (const float*)d_in[9];
    float* out = (float*)d_out;

    dim3 gq(OUTC/128, TOK/128, 2);      // 3 x 196 x 2
    qkv_kernel<<<gq, dim3(16,16)>>>(x, y, wqx, bqx, wqy, bqy);
    mean_kernel <<<2*NB*P2, 128>>>();
    route_kernel<<<2*NB*P2, 64>>>();
    attn_kernel <<<dim3(NB*P2, HEADS/2, 2), 64>>>(out);
    lepe_kernel <<<2*NB*HW*HW, 128>>>(wlx, blx, wly, bly, out);
}

// round 17
// speedup vs baseline: 1.0849x; 1.0849x over previous
#include <cuda_runtime.h>

#define NB    8
#define HW    56
#define CDIM  128
#define P2    49
#define PIX   64
#define QKC   128
#define KVC   256
#define OUTC  384
#define TOK   (NB*HW*HW)   /* 25088 */
#define NTOPK 4
#define HEADS 8
#define HD    16

typedef unsigned long long u64t;

// ---- packed f32x2 helpers (Blackwell sm_103a) ------------------------------
__device__ __forceinline__ u64t pack2(float lo, float hi) {
    u64t r; asm("mov.b64 %0, {%1, %2};" : "=l"(r) : "f"(lo), "f"(hi)); return r;
}
__device__ __forceinline__ void unpack2(u64t v, float& lo, float& hi) {
    asm("mov.b64 {%0, %1}, %2;" : "=f"(lo), "=f"(hi) : "l"(v));
}
__device__ __forceinline__ void fma2(u64t& d, u64t a, u64t b) {
    asm("fma.rn.f32x2 %0, %1, %2, %0;" : "+l"(d) : "l"(a), "l"(b));
}
__device__ __forceinline__ void mul2(u64t& d, u64t a) {
    asm("mul.rn.f32x2 %0, %0, %1;" : "+l"(d) : "l"(a));
}
__device__ __forceinline__ float ex2a(float x) {
    float r; asm("ex2.approx.f32 %0, %1;" : "=f"(r) : "f"(x)); return r;
}
__device__ __forceinline__ void cp16(void* smem, const void* gmem) {
    unsigned s = (unsigned)__cvta_generic_to_shared(smem);
    asm volatile("cp.async.cg.shared.global [%0], [%1], 16;" :: "r"(s), "l"(gmem));
}
__device__ __forceinline__ void cp_commit() {
    asm volatile("cp.async.commit_group;");
}
__device__ __forceinline__ void cp_wait0() {
    asm volatile("cp.async.wait_group 0;");
}
__device__ __forceinline__ void cp_wait1() {
    asm volatile("cp.async.wait_group 1;");
}

// ---------------- scratch (device globals; no runtime allocation) ----------
__device__ float g_q   [2][NB][P2][PIX][QKC];   // per-branch q, windowed
__device__ float g_kv  [2][NB][P2][PIX][KVC];   // per-branch kv, windowed
__device__ float g_vimg[2][NB][HW][HW][CDIM];   // v in image layout (for LePE)
__device__ float g_qwin[2][NB][P2][QKC];
__device__ float g_kwin[2][NB][P2][QKC];
__device__ int   g_top [2][NB][P2][NTOPK];

// ---------------- 1. QKV projection GEMM (both branches, f32x2) ------------
// 128x128 tile, 16-wide k-tiles. Proven R5 compute loop (in-loop packs).
// New: W tiles double-buffered via cp.async, A tiles register-prefetched,
// so global-load latency hides under the compute phase.
__global__ void __launch_bounds__(256) qkv_kernel(
        const float* __restrict__ x, const float* __restrict__ y,
        const float* __restrict__ wx, const float* __restrict__ bx,
        const float* __restrict__ wy, const float* __restrict__ by)
{
    const int br = blockIdx.z;
    const float* __restrict__ A  = br ? y  : x;
    const float* __restrict__ W  = br ? wy : wx;
    const float* __restrict__ Bv = br ? by : bx;

    const int t0 = blockIdx.y * 128;   // token tile
    const int c0 = blockIdx.x * 128;   // output-channel tile

    __shared__ float As[16][132];      // A transposed: As[k][row] (single buf)
    __shared__ float Bs[2][16][136];   // W: Bs[buf][k][col] (double buf)

    const int tx = threadIdx.x, ty = threadIdx.y;   // 16 x 16
    const int tid = ty * 16 + tx;

    // A: 128 rows x 16 k; 2 thr/row, 8 k each. W: 16 rows x 128 cols; 8 cols/thr.
    const int arow = tid >> 1,  ak0 = (tid & 1)  * 8;
    const int brow = tid >> 4,  bc0 = (tid & 15) * 8;

    const float* aptr = &A[(long)(t0 + arow) * CDIM + ak0];
    const float* wptr = &W[(long)brow * OUTC + c0 + bc0];

    u64t acc[8][4];
    #pragma unroll
    for (int i = 0; i < 8; i++)
        #pragma unroll
        for (int j = 0; j < 4; j++) acc[i][j] = 0ull;

    // prologue: A tile0 to regs, W tile0 via cp.async
    float4 pa0 = *reinterpret_cast<const float4*>(aptr);
    float4 pa1 = *reinterpret_cast<const float4*>(aptr + 4);
    cp16(&Bs[0][brow][bc0],     wptr);
    cp16(&Bs[0][brow][bc0 + 4], wptr + 4);
    cp_commit();

    #pragma unroll 1
    for (int it = 0; it < 8; it++) {
        const int buf = it & 1;
        // store A regs (transposed) — previous compute finished at the
        // trailing barrier of the prior iteration.
        As[ak0 + 0][arow] = pa0.x;
        As[ak0 + 1][arow] = pa0.y;
        As[ak0 + 2][arow] = pa0.z;
        As[ak0 + 3][arow] = pa0.w;
        As[ak0 + 4][arow] = pa1.x;
        As[ak0 + 5][arow] = pa1.y;
        As[ak0 + 6][arow] = pa1.z;
        As[ak0 + 7][arow] = pa1.w;
        cp_wait0();                    // W(it) resident
        __syncthreads();               // As + Bs[buf] visible to all

        if (it < 7) {                  // prefetch next tile (overlaps compute)
            const int k1 = (it + 1) * 16;
            pa0 = *reinterpret_cast<const float4*>(aptr + k1);
            pa1 = *reinterpret_cast<const float4*>(aptr + k1 + 4);
            const float* wp = wptr + (long)k1 * OUTC;
            cp16(&Bs[buf ^ 1][brow][bc0],     wp);
            cp16(&Bs[buf ^ 1][brow][bc0 + 4], wp + 4);
            cp_commit();
        }

        #pragma unroll
        for (int kk = 0; kk < 16; kk++) {
            float4 a0 = *reinterpret_cast<const float4*>(&As[kk][ty*4]);
            float4 a1 = *reinterpret_cast<const float4*>(&As[kk][64 + ty*4]);
            ulonglong2 b0 = *reinterpret_cast<const ulonglong2*>(&Bs[buf][kk][tx*4]);
            ulonglong2 b1 = *reinterpret_cast<const ulonglong2*>(&Bs[buf][kk][64 + tx*4]);
            u64t bp[4] = { b0.x, b0.y, b1.x, b1.y };
            u64t ap[8];
            ap[0]=pack2(a0.x,a0.x); ap[1]=pack2(a0.y,a0.y);
            ap[2]=pack2(a0.z,a0.z); ap[3]=pack2(a0.w,a0.w);
            ap[4]=pack2(a1.x,a1.x); ap[5]=pack2(a1.y,a1.y);
            ap[6]=pack2(a1.z,a1.z); ap[7]=pack2(a1.w,a1.w);
            #pragma unroll
            for (int i = 0; i < 8; i++)
                #pragma unroll
                for (int j = 0; j < 4; j++)
                    fma2(acc[i][j], ap[i], bp[j]);
        }
        __syncthreads();               // protect As overwrite next iteration
    }

    // epilogue: scatter into windowed layouts
    #pragma unroll
    for (int i = 0; i < 8; i++) {
        int t   = t0 + (i < 4 ? ty*4 + i : 64 + ty*4 + i - 4);
        int n   = t / (HW*HW);
        int rem = t % (HW*HW);
        int Y = rem / HW, X = rem % HW;
        int p   = (Y >> 3) * 7 + (X >> 3);
        int pix = (Y & 7) * 8 + (X & 7);
        #pragma unroll
        for (int jb = 0; jb < 4; jb++) {
            float v0, v1;
            unpack2(acc[i][jb], v0, v1);
            int cbase = c0 + (jb < 2 ? tx*4 + jb*2 : 64 + tx*4 + (jb-2)*2);
            #pragma unroll
            for (int h = 0; h < 2; h++) {
                int cc = cbase + h;
                float v = (h ? v1 : v0) + Bv[cc];
                if (cc < QKC) {
                    g_q[br][n][p][pix][cc] = v;
                } else {
                    g_kv[br][n][p][pix][cc - QKC] = v;
                    if (cc >= 256) g_vimg[br][n][Y][X][cc - 256] = v;
                }
            }
        }
    }
}

// ---------------- 2. window means ------------------------------------------
__global__ void mean_kernel()
{
    int b   = blockIdx.x;               // 2*NB*P2
    int br  = b / (NB*P2);
    int rem = b % (NB*P2);
    int n = rem / P2, p = rem % P2;
    int c = threadIdx.x;                // 128
    float sq = 0.f, sk = 0.f;
    #pragma unroll 8
    for (int pix = 0; pix < PIX; pix++) {
        sq += g_q [br][n][p][pix][c];
        sk += g_kv[br][n][p][pix][c];
    }
    g_qwin[br][n][p][c] = sq * (1.f/64.f);
    g_kwin[br][n][p][c] = sk * (1.f/64.f);
}

// ---------------- 3. routing: exact top-4 (jax top_k ordering) -------------
__global__ void route_kernel()
{
    int b   = blockIdx.x;               // 2*NB*P2
    int br  = b / (NB*P2);
    int rem = b % (NB*P2);
    int n = rem / P2, p = rem % P2;

    __shared__ float lg[P2];
    int j = threadIdx.x;                // 64 threads
    if (j < P2) {
        float d = 0.f;
        #pragma unroll 8
        for (int c = 0; c < QKC; c++)
            d += g_qwin[br][n][p][c] * g_kwin[br][n][j][c];
        lg[j] = d;   // positive scale doesn't change ordering
    }
    __syncthreads();
    if (threadIdx.x == 0) {
        bool used[P2];
        #pragma unroll
        for (int q = 0; q < P2; q++) used[q] = false;
        for (int k = 0; k < NTOPK; k++) {
            float best = -3.4e38f; int bi = 0;
            for (int q = 0; q < P2; q++)
                if (!used[q] && lg[q] > best) { best = lg[q]; bi = q; }
            used[bi] = true;
            g_top[br][n][p][k] = bi;
        }
    }
}

// ---------------- 4. fused gather + cross attention ------------------------
// Block = (n,p,dir) x head-pair; warp = one head, fully independent:
// per-warp double-buffered cp.async staging (32-key stages), no block barriers.
// Thread = 2 queries (lane, lane+32), all math packed f32x2.
// Softmax without max-shift; scale*log2e folded into q (single EX2 per key).
__global__ void __launch_bounds__(64, 8) attn_kernel(float* __restrict__ out)
{
    const int np = blockIdx.x;          // 392
    const int n = np / P2, p = np % P2;
    const int hp  = blockIdx.y;         // head pair 0..3
    const int dir = blockIdx.z;
    const int Abr = dir ^ 1;            // dir0: A=1, dir1: A=0
    const int Bbr = dir;                // dir0: B=0, dir1: B=1

    // per-warp staging: [warp][buf][32 rows x 4 x 16B]
    __shared__ ulonglong2 kbuf[2][2][128];
    __shared__ ulonglong2 vbuf[2][2][128];
    __shared__ int swA[4], swB[4];

    const int tid  = threadIdx.x;       // 64
    const int warp = tid >> 5;
    const int lane = tid & 31;
    const int head = hp * 2 + warp;
    const int hc   = head * HD;

    if (tid < 4)      swA[tid]   = g_top[Abr][n][p][tid];
    else if (tid < 8) swB[tid-4] = g_top[Bbr][n][p][tid-4];

    const float* __restrict__ kvA = &g_kv[Abr][n][0][0][0];
    const float* __restrict__ kvB = &g_kv[Bbr][n][0][0][0];

    // load the two queries (pixels lane, lane+32), pre-scaled by scale*log2e
    const float qsc = 0.0883883476483184405f * 1.44269504088896340736f;
    const u64t qsc2 = pack2(qsc, qsc);
    u64t qA[8], qB[8];
    {
        const ulonglong2* qp = (const ulonglong2*)&g_q[Abr][n][p][lane][hc];
        #pragma unroll
        for (int i = 0; i < 4; i++) { ulonglong2 t = qp[i]; qA[2*i] = t.x; qA[2*i+1] = t.y; }
        qp = (const ulonglong2*)&g_q[Abr][n][p][lane + 32][hc];
        #pragma unroll
        for (int i = 0; i < 4; i++) { ulonglong2 t = qp[i]; qB[2*i] = t.x; qB[2*i+1] = t.y; }
        #pragma unroll
        for (int i = 0; i < 8; i++) { mul2(qA[i], qsc2); mul2(qB[i], qsc2); }
    }
    __syncthreads();                    // widx visible to all warps (only block barrier)

    // hoist gathered-window base pointers into registers (per-thread)
    const float* baseA[4];
    const float* baseB[4];
    #pragma unroll
    for (int kk = 0; kk < 4; kk++) {
        baseA[kk] = kvA + (long)swA[kk] * PIX * KVC + hc;
        baseB[kk] = kvB + (long)swB[kk] * PIX * KVC + QKC + hc;
    }

    // prefetch helper: stage st (32 keys) into buffer b
    auto prefetch = [&](int st, int b) {
        #pragma unroll
        for (int l = 0; l < 4; l++) {
            int e   = lane + l * 32;    // 0..127 float4 slots
            int row = e >> 2, c4 = e & 3;
            int grow = st * 32 + row;
            int kk = grow >> 6, pix = grow & 63;
            long off = (long)pix * KVC + c4 * 4;
            cp16(&kbuf[warp][b][e], baseA[kk] + off);
            cp16(&vbuf[warp][b][e], baseB[kk] + off);
        }
    };

    float sA = 0.f, sB = 0.f;
    u64t oA[8], oB[8];
    #pragma unroll
    for (int i = 0; i < 8; i++) { oA[i] = 0ull; oB[i] = 0ull; }

    prefetch(0, 0);
    cp_commit();

    for (int st = 0; st < 8; st++) {
        if (st < 7) prefetch(st + 1, (st + 1) & 1);
        cp_commit();                    // may be an empty group on st==7
        cp_wait1();                     // stage st complete (<=1 group pending)
        __syncwarp();

        const ulonglong2* kb = &kbuf[warp][st & 1][0];
        const ulonglong2* vb = &vbuf[warp][st & 1][0];

        #pragma unroll 8
        for (int j = 0; j < 32; j++) {
            const ulonglong2* kr = kb + j * 4;
            ulonglong2 r0 = kr[0], r1 = kr[1], r2 = kr[2], r3 = kr[3];
            u64t dA = 0ull, dB = 0ull;
            fma2(dA, qA[0], r0.x); fma2(dB, qB[0], r0.x);
            fma2(dA, qA[1], r0.y); fma2(dB, qB[1], r0.y);
            fma2(dA, qA[2], r1.x); fma2(dB, qB[2], r1.x);
            fma2(dA, qA[3], r1.y); fma2(dB, qB[3], r1.y);
            fma2(dA, qA[4], r2.x); fma2(dB, qB[4], r2.x);
            fma2(dA, qA[5], r2.y); fma2(dB, qB[5], r2.y);
            fma2(dA, qA[6], r3.x); fma2(dB, qB[6], r3.x);
            fma2(dA, qA[7], r3.y); fma2(dB, qB[7], r3.y);
            float l0, l1, lgA, lgB;
            unpack2(dA, l0, l1); lgA = l0 + l1;
            unpack2(dB, l0, l1); lgB = l0 + l1;
            float pA = ex2a(lgA);       // exp(logit), base-2 folded into q
            float pB = ex2a(lgB);
            sA += pA; sB += pB;
            u64t pA2 = pack2(pA, pA), pB2 = pack2(pB, pB);
            const ulonglong2* vr = vb + j * 4;
            ulonglong2 v0 = vr[0], v1 = vr[1], v2 = vr[2], v3 = vr[3];
            fma2(oA[0], pA2, v0.x); fma2(oB[0], pB2, v0.x);
            fma2(oA[1], pA2, v0.y); fma2(oB[1], pB2, v0.y);
            fma2(oA[2], pA2, v1.x); fma2(oB[2], pB2, v1.x);
            fma2(oA[3], pA2, v1.y); fma2(oB[3], pB2, v1.y);
            fma2(oA[4], pA2, v2.x); fma2(oB[4], pB2, v2.x);
            fma2(oA[5], pA2, v2.y); fma2(oB[5], pB2, v2.y);
            fma2(oA[6], pA2, v3.x); fma2(oB[6], pB2, v3.x);
            fma2(oA[7], pA2, v3.y); fma2(oB[7], pB2, v3.y);
        }
        __syncwarp();                   // all lanes done reading before next overwrite
    }

    const float invA = 1.f / sA, invB = 1.f / sB;
    u64t iA2 = pack2(invA, invA), iB2 = pack2(invB, invB);
    #pragma unroll
    for (int i = 0; i < 8; i++) { mul2(oA[i], iA2); mul2(oB[i], iB2); }

    const int Yb = (p / 7) * 8, Xb = (p % 7) * 8;
    {
        int Y = Yb + (lane >> 3), X = Xb + (lane & 7);
        float* op = out + (long)dir * TOK * CDIM
                  + ((long)(n * HW + Y) * HW + X) * CDIM + hc;
        ulonglong2* o2 = (ulonglong2*)op;
        o2[0] = make_ulonglong2(oA[0], oA[1]);
        o2[1] = make_ulonglong2(oA[2], oA[3]);
        o2[2] = make_ulonglong2(oA[4], oA[5]);
        o2[3] = make_ulonglong2(oA[6], oA[7]);
    }
    {
        int qpix = lane + 32;
        int Y = Yb + (qpix >> 3), X = Xb + (qpix & 7);
        float* op = out + (long)dir * TOK * CDIM
                  + ((long)(n * HW + Y) * HW + X) * CDIM + hc;
        ulonglong2* o2 = (ulonglong2*)op;
        o2[0] = make_ulonglong2(oB[0], oB[1]);
        o2[1] = make_ulonglong2(oB[2], oB[3]);
        o2[2] = make_ulonglong2(oB[4], oB[5]);
        o2[3] = make_ulonglong2(oB[6], oB[7]);
    }
}

// ---------------- 5. LePE depthwise 3x3 conv (accumulate into out) ---------
__global__ void lepe_kernel(const float* __restrict__ wlx, const float* __restrict__ blx,
                            const float* __restrict__ wly, const float* __restrict__ bly,
                            float* __restrict__ out)
{
    int b   = blockIdx.x;               // 2*NB*HW*HW
    int br  = b / (NB*HW*HW);
    int rem = b % (NB*HW*HW);
    int n  = rem / (HW*HW);
    int r2 = rem % (HW*HW);
    int Y = r2 / HW, X = r2 % HW;
    int c = threadIdx.x;                // 128
    const float* __restrict__ wl = br ? wly : wlx;
    const float* __restrict__ bl = br ? bly : blx;

    float acc = bl[c];
    #pragma unroll
    for (int dy = 0; dy < 3; dy++) {
        int Yn = Y + dy - 1;
        if (Yn < 0 || Yn >= HW) continue;
        #pragma unroll
        for (int dx = 0; dx < 3; dx++) {
            int Xn = X + dx - 1;
            if (Xn < 0 || Xn >= HW) continue;
            acc += g_vimg[br][n][Yn][Xn][c] * wl[c*9 + dy*3 + dx];
        }
    }
    long off = (long)br * TOK * CDIM + (long)rem * CDIM + c;
    out[off] += acc;
}

// ---------------- launch ----------------------------------------------------
extern "C" void kernel_launch(void* const* d_in, const int* in_sizes, int n_in,
                              void* d_out, int out_size)
{
    const float* x   = (const float*)d_in[0];
    const float* y   = (const float*)d_in[1];
    const float* wqx = (const float*)d_in[2];
    const float* bqx = (const float*)d_in[3];
    const float* wqy = (const float*)d_in[4];
    const float* bqy = (const float*)d_in[5];
    const float* wlx = (const float*)d_in[6];
    const float* blx = (const float*)d_in[7];
    const float* wly = (const float*)d_in[8];
    const float* bly = (const float*)d_in[9];
    float* out = (float*)d_out;

    dim3 gq(OUTC/128, TOK/128, 2);      // 3 x 196 x 2
    qkv_kernel<<<gq, dim3(16,16)>>>(x, y, wqx, bqx, wqy, bqy);
    mean_kernel <<<2*NB*P2, 128>>>();
    route_kernel<<<2*NB*P2, 64>>>();
    attn_kernel <<<dim3(NB*P2, HEADS/2, 2), 64>>>(out);
    lepe_kernel <<<2*NB*HW*HW, 128>>>(wlx, blx, wly, bly, out);
}